// round 4
// baseline (speedup 1.0000x reference)
#include <cuda_runtime.h>
#include <cuda_bf16.h>
#include <math.h>

// Shapes (fixed by problem)
#define B   256
#define S   196
#define D   1024
#define P   512
#define L   8
#define TOPK 4
#define SPLITK 8     // K3 split-K factor (1024/8 = 128 per split)

// Scratch (device globals; no allocation allowed)
__device__ float g_qn[B * D];            // normalized query   [B,D]   1 MB
__device__ float g_kn[P * D];            // normalized keys    [P,D]   2 MB
__device__ float g_simp[SPLITK * B * P]; // split-K partials   [8,B,P] 4 MB

// ---------------------------------------------------------------------------
// K1: query = mean_s(x_embed[b]) ; qn = l2norm(query)
// One block per b, 256 threads, each thread owns 4 contiguous d (float4).
// Memory-bound: streams 205 MB.
// ---------------------------------------------------------------------------
__global__ __launch_bounds__(256) void k_query_mean_norm(const float* __restrict__ x)
{
    const int b = blockIdx.x;
    const int t = threadIdx.x;
    const float4* __restrict__ xp = (const float4*)(x + (size_t)b * S * D) + t; // stride D/4

    float4 acc = make_float4(0.f, 0.f, 0.f, 0.f);
#pragma unroll 4
    for (int s = 0; s < S; ++s) {
        float4 v = xp[(size_t)s * (D / 4)];
        acc.x += v.x; acc.y += v.y; acc.z += v.z; acc.w += v.w;
    }
    const float inv_s = 1.0f / (float)S;
    acc.x *= inv_s; acc.y *= inv_s; acc.z *= inv_s; acc.w *= inv_s;

    float sq = acc.x * acc.x + acc.y * acc.y + acc.z * acc.z + acc.w * acc.w;
    // block reduction of sq
#pragma unroll
    for (int off = 16; off; off >>= 1) sq += __shfl_down_sync(0xFFFFFFFFu, sq, off);
    __shared__ float red[8];
    __shared__ float s_inv;
    if ((t & 31) == 0) red[t >> 5] = sq;
    __syncthreads();
    if (t == 0) {
        float tot = 0.f;
#pragma unroll
        for (int w = 0; w < 8; ++w) tot += red[w];
        s_inv = rsqrtf(fmaxf(tot, 1e-12f));
    }
    __syncthreads();
    const float inv = s_inv;
    float4 o = make_float4(acc.x * inv, acc.y * inv, acc.z * inv, acc.w * inv);
    ((float4*)g_qn)[b * (D / 4) + t] = o;
}

// ---------------------------------------------------------------------------
// K2: kn = l2norm(prompt_key) per row. One block per p, 256 threads x float4.
// ---------------------------------------------------------------------------
__global__ __launch_bounds__(256) void k_key_norm(const float* __restrict__ pk)
{
    const int p = blockIdx.x;
    const int t = threadIdx.x;
    float4 v = ((const float4*)(pk + (size_t)p * D))[t];
    float sq = v.x * v.x + v.y * v.y + v.z * v.z + v.w * v.w;
#pragma unroll
    for (int off = 16; off; off >>= 1) sq += __shfl_down_sync(0xFFFFFFFFu, sq, off);
    __shared__ float red[8];
    __shared__ float s_inv;
    if ((t & 31) == 0) red[t >> 5] = sq;
    __syncthreads();
    if (t == 0) {
        float tot = 0.f;
#pragma unroll
        for (int w = 0; w < 8; ++w) tot += red[w];
        s_inv = rsqrtf(fmaxf(tot, 1e-12f));
    }
    __syncthreads();
    const float inv = s_inv;
    float4 o = make_float4(v.x * inv, v.y * inv, v.z * inv, v.w * inv);
    ((float4*)g_kn)[p * (D / 4) + t] = o;
}

// ---------------------------------------------------------------------------
// K3: sim_part[z] = qn[64 rows] * kn[64 rows]^T over K-chunk 128.
// Tiles: BM=64, BN=64, BK=32; grid (4, 8, 8) = 256 blocks; 256 threads;
// 4x4 register microtile per thread; both operands staged transposed (k-major)
// in shared so the inner loop is 2x LDS.128 + 16 FFMA per k.
// ---------------------------------------------------------------------------
__global__ __launch_bounds__(256) void k_sim_gemm()
{
    __shared__ float As[32][68];
    __shared__ float Bs[32][68];

    const int m0 = blockIdx.x * 64;
    const int n0 = blockIdx.y * 64;
    const int kbase = blockIdx.z * (D / SPLITK); // 128

    const int tid = threadIdx.x;
    const int lr = tid >> 2;         // 0..63 : tile row loaded by this thread
    const int lk = (tid & 3) * 8;    // 0,8,16,24 : k offset (8 floats)
    const int tr = tid >> 4;         // 0..15 : m-group
    const int tc = tid & 15;         // 0..15 : n-group

    float acc[4][4] = {};

    for (int kb = 0; kb < D / SPLITK; kb += 32) {
        const int k0 = kbase + kb;
        // global loads first (hide latency over the barrier)
        const float4 a0 = *(const float4*)&g_qn[(m0 + lr) * D + k0 + lk];
        const float4 a1 = *(const float4*)&g_qn[(m0 + lr) * D + k0 + lk + 4];
        const float4 b0 = *(const float4*)&g_kn[(n0 + lr) * D + k0 + lk];
        const float4 b1 = *(const float4*)&g_kn[(n0 + lr) * D + k0 + lk + 4];
        __syncthreads();   // previous iteration's reads done
        As[lk + 0][lr] = a0.x; As[lk + 1][lr] = a0.y; As[lk + 2][lr] = a0.z; As[lk + 3][lr] = a0.w;
        As[lk + 4][lr] = a1.x; As[lk + 5][lr] = a1.y; As[lk + 6][lr] = a1.z; As[lk + 7][lr] = a1.w;
        Bs[lk + 0][lr] = b0.x; Bs[lk + 1][lr] = b0.y; Bs[lk + 2][lr] = b0.z; Bs[lk + 3][lr] = b0.w;
        Bs[lk + 4][lr] = b1.x; Bs[lk + 5][lr] = b1.y; Bs[lk + 6][lr] = b1.z; Bs[lk + 7][lr] = b1.w;
        __syncthreads();

#pragma unroll
        for (int k = 0; k < 32; ++k) {
            const float4 av = *(const float4*)&As[k][tr * 4];
            const float4 bv = *(const float4*)&Bs[k][tc * 4];
            const float a[4] = {av.x, av.y, av.z, av.w};
            const float bb[4] = {bv.x, bv.y, bv.z, bv.w};
#pragma unroll
            for (int i = 0; i < 4; ++i)
#pragma unroll
                for (int j = 0; j < 4; ++j)
                    acc[i][j] = fmaf(a[i], bb[j], acc[i][j]);
        }
    }

#pragma unroll
    for (int i = 0; i < 4; ++i) {
        float4 r = make_float4(acc[i][0], acc[i][1], acc[i][2], acc[i][3]);
        *(float4*)&g_simp[((size_t)blockIdx.z * B + (m0 + tr * 4 + i)) * P + n0 + tc * 4] = r;
    }
}

// ---------------------------------------------------------------------------
// K4: per batch row — reduce split-K partials, 4 rounds of gumbel argmax with
// -1000 masking (STE forward == one-hot), then gather-copy prompt rows to out.
// One block per b, 256 threads.
// ---------------------------------------------------------------------------
__global__ __launch_bounds__(256) void k_select_copy(const float* __restrict__ prompt,
                                                     const float* __restrict__ gu,
                                                     float* __restrict__ out)
{
    __shared__ float cur[P];
    __shared__ float warpv[8];
    __shared__ int   warpi[8];
    __shared__ int   s_sel;

    const int b = blockIdx.x;
    const int t = threadIdx.x;

    // split-K reduce (fixed order -> deterministic)
#pragma unroll
    for (int p = t; p < P; p += 256) {
        float s = 0.f;
#pragma unroll
        for (int z = 0; z < SPLITK; ++z) s += g_simp[((size_t)z * B + b) * P + p];
        cur[p] = s;
    }
    __syncthreads();

    int chosen[TOPK];
#pragma unroll
    for (int i = 0; i < TOPK; ++i) {
        float bestv = -INFINITY;
        int   besti = P;  // larger than any valid index
#pragma unroll
        for (int p = t; p < P; p += 256) {
            float u = gu[(((size_t)i * B) + b) * P + p];
            float g = -logf(-logf(u + 1e-10f) + 1e-10f);
            float v = cur[p] + g;
            if (v > bestv || (v == bestv && p < besti)) { bestv = v; besti = p; }
        }
#pragma unroll
        for (int off = 16; off; off >>= 1) {
            float ov = __shfl_down_sync(0xFFFFFFFFu, bestv, off);
            int   oi = __shfl_down_sync(0xFFFFFFFFu, besti, off);
            if (ov > bestv || (ov == bestv && oi < besti)) { bestv = ov; besti = oi; }
        }
        if ((t & 31) == 0) { warpv[t >> 5] = bestv; warpi[t >> 5] = besti; }
        __syncthreads();
        if (t == 0) {
            float bv = warpv[0]; int bi = warpi[0];
#pragma unroll
            for (int w = 1; w < 8; ++w)
                if (warpv[w] > bv || (warpv[w] == bv && warpi[w] < bi)) { bv = warpv[w]; bi = warpi[w]; }
            s_sel = bi;
            cur[bi] -= 1000.0f;   // mask selected entry (w*1000 ~ 1000 within 1e-4; irrelevant post -1000)
        }
        __syncthreads();
        chosen[i] = s_sel;
    }

    // gather: out[b, i*L + l, :] = prompt[chosen[i], l, :]
    float4* __restrict__ outb = (float4*)(out + (size_t)b * TOPK * L * D);
#pragma unroll
    for (int i = 0; i < TOPK; ++i) {
        const float4* __restrict__ src = (const float4*)(prompt + (size_t)chosen[i] * L * D);
        float4* __restrict__ dst = outb + i * (L * D / 4);
#pragma unroll
        for (int r = 0; r < (L * D / 4) / 256; ++r)   // 8 float4 per thread
            dst[t + r * 256] = src[t + r * 256];
    }
}

// ---------------------------------------------------------------------------
extern "C" void kernel_launch(void* const* d_in, const int* in_sizes, int n_in,
                              void* d_out, int out_size)
{
    const float* x      = (const float*)d_in[0]; // [B,S,D]
    const float* prompt = (const float*)d_in[1]; // [P,L,D]
    const float* pkey   = (const float*)d_in[2]; // [P,D]
    const float* gu     = (const float*)d_in[3]; // [TOPK,B,P]
    float* out          = (float*)d_out;         // [B, TOPK*L, D]

    k_query_mean_norm<<<B, 256>>>(x);
    k_key_norm<<<P, 256>>>(pkey);
    k_sim_gemm<<<dim3(B / 64, P / 64, SPLITK), 256>>>();
    k_select_copy<<<B, 256>>>(prompt, gu, out);
}

// round 9
// speedup vs baseline: 1.0827x; 1.0827x over previous
#include <cuda_runtime.h>
#include <cuda_bf16.h>
#include <math.h>

// Shapes (fixed by problem)
#define B    256
#define S    196
#define D    1024
#define P    512
#define L    8
#define TOPK 4
#define SPLITK 8      // GEMM split-K (1024/8 = 128 per split)
#define SCHUNK 4      // K1 split over S (196/4 = 49 rows per chunk)

// Scratch (device globals; no allocation allowed)
__device__ float g_part[B * SCHUNK * D];   // K1 partial sums   [B,4,D]  4 MB
__device__ float g_qn[B * D];              // normalized query  [B,D]    1 MB
__device__ float g_kn[P * D];              // normalized keys   [P,D]    2 MB
__device__ float g_simp[SPLITK * B * P];   // split-K partials  [8,B,P]  4 MB
__device__ int   g_sel[B * TOPK];          // chosen prompt indices

// ---------------------------------------------------------------------------
// K1a: partial sums over 49-row chunks of S.  grid (B, SCHUNK), 256 threads.
// Each block streams 49 contiguous 4KB rows; 1024 blocks => ~28 warps/SM.
// ---------------------------------------------------------------------------
__global__ __launch_bounds__(256) void k1a_partial(const float* __restrict__ x)
{
    const int b = blockIdx.x;
    const int c = blockIdx.y;
    const int t = threadIdx.x;
    const float4* __restrict__ xp =
        (const float4*)(x + ((size_t)b * S + c * (S / SCHUNK)) * D) + t;

    float4 acc = make_float4(0.f, 0.f, 0.f, 0.f);
#pragma unroll 7
    for (int s = 0; s < S / SCHUNK; ++s) {
        float4 v = xp[(size_t)s * (D / 4)];
        acc.x += v.x; acc.y += v.y; acc.z += v.z; acc.w += v.w;
    }
    ((float4*)g_part)[((size_t)(b * SCHUNK + c) * D) / 4 + t] = acc;
}

// ---------------------------------------------------------------------------
// K1b+K2 fused: blocks [0,B) finalize query (reduce 4 partials, /S, l2norm);
// blocks [B, B+P) l2-normalize prompt_key rows.  256 threads = D/4 float4s.
// ---------------------------------------------------------------------------
__global__ __launch_bounds__(256) void k_norms(const float* __restrict__ pk)
{
    __shared__ float red[8];
    __shared__ float s_inv;
    const int blk = blockIdx.x;
    const int t = threadIdx.x;

    float4 v;
    float* dst;
    if (blk < B) {
        const float4* pp = (const float4*)g_part + (size_t)blk * SCHUNK * (D / 4) + t;
        float4 a0 = pp[0 * (D / 4)], a1 = pp[1 * (D / 4)];
        float4 a2 = pp[2 * (D / 4)], a3 = pp[3 * (D / 4)];
        const float inv_s = 1.0f / (float)S;
        v.x = (a0.x + a1.x + a2.x + a3.x) * inv_s;
        v.y = (a0.y + a1.y + a2.y + a3.y) * inv_s;
        v.z = (a0.z + a1.z + a2.z + a3.z) * inv_s;
        v.w = (a0.w + a1.w + a2.w + a3.w) * inv_s;
        dst = g_qn + (size_t)blk * D;
    } else {
        const int p = blk - B;
        v = ((const float4*)(pk + (size_t)p * D))[t];
        dst = g_kn + (size_t)p * D;
    }

    float sq = v.x * v.x + v.y * v.y + v.z * v.z + v.w * v.w;
#pragma unroll
    for (int off = 16; off; off >>= 1) sq += __shfl_down_sync(0xFFFFFFFFu, sq, off);
    if ((t & 31) == 0) red[t >> 5] = sq;
    __syncthreads();
    if (t == 0) {
        float tot = 0.f;
#pragma unroll
        for (int w = 0; w < 8; ++w) tot += red[w];
        s_inv = rsqrtf(fmaxf(tot, 1e-12f));
    }
    __syncthreads();
    const float inv = s_inv;
    ((float4*)dst)[t] = make_float4(v.x * inv, v.y * inv, v.z * inv, v.w * inv);
}

// ---------------------------------------------------------------------------
// K3: split-K SGEMM  sim = qn * kn^T.  BM=64,BN=64,BK=32; grid (4,8,8);
// 256 threads; 4x4 register microtile; operands staged k-major in shared.
// ---------------------------------------------------------------------------
__global__ __launch_bounds__(256) void k_sim_gemm()
{
    __shared__ float As[32][68];
    __shared__ float Bs[32][68];

    const int m0 = blockIdx.x * 64;
    const int n0 = blockIdx.y * 64;
    const int kbase = blockIdx.z * (D / SPLITK);

    const int tid = threadIdx.x;
    const int lr = tid >> 2;
    const int lk = (tid & 3) * 8;
    const int tr = tid >> 4;
    const int tc = tid & 15;

    float acc[4][4] = {};

    for (int kb = 0; kb < D / SPLITK; kb += 32) {
        const int k0 = kbase + kb;
        const float4 a0 = *(const float4*)&g_qn[(m0 + lr) * D + k0 + lk];
        const float4 a1 = *(const float4*)&g_qn[(m0 + lr) * D + k0 + lk + 4];
        const float4 b0 = *(const float4*)&g_kn[(n0 + lr) * D + k0 + lk];
        const float4 b1 = *(const float4*)&g_kn[(n0 + lr) * D + k0 + lk + 4];
        __syncthreads();
        As[lk + 0][lr] = a0.x; As[lk + 1][lr] = a0.y; As[lk + 2][lr] = a0.z; As[lk + 3][lr] = a0.w;
        As[lk + 4][lr] = a1.x; As[lk + 5][lr] = a1.y; As[lk + 6][lr] = a1.z; As[lk + 7][lr] = a1.w;
        Bs[lk + 0][lr] = b0.x; Bs[lk + 1][lr] = b0.y; Bs[lk + 2][lr] = b0.z; Bs[lk + 3][lr] = b0.w;
        Bs[lk + 4][lr] = b1.x; Bs[lk + 5][lr] = b1.y; Bs[lk + 6][lr] = b1.z; Bs[lk + 7][lr] = b1.w;
        __syncthreads();

#pragma unroll
        for (int k = 0; k < 32; ++k) {
            const float4 av = *(const float4*)&As[k][tr * 4];
            const float4 bv = *(const float4*)&Bs[k][tc * 4];
            const float a[4] = {av.x, av.y, av.z, av.w};
            const float bb[4] = {bv.x, bv.y, bv.z, bv.w};
#pragma unroll
            for (int i = 0; i < 4; ++i)
#pragma unroll
                for (int j = 0; j < 4; ++j)
                    acc[i][j] = fmaf(a[i], bb[j], acc[i][j]);
        }
    }

#pragma unroll
    for (int i = 0; i < 4; ++i) {
        float4 r = make_float4(acc[i][0], acc[i][1], acc[i][2], acc[i][3]);
        *(float4*)&g_simp[((size_t)blockIdx.z * B + (m0 + tr * 4 + i)) * P + n0 + tc * 4] = r;
    }
}

// ---------------------------------------------------------------------------
// K4a: per-b selection only.  Reduce split-K partials, 4 gumbel-argmax rounds
// with -1000 masking (STE forward == one-hot).  grid B, 256 threads.
// ---------------------------------------------------------------------------
__global__ __launch_bounds__(256) void k_select(const float* __restrict__ gu)
{
    __shared__ float cur[P];
    __shared__ float warpv[8];
    __shared__ int   warpi[8];
    __shared__ int   s_sel;

    const int b = blockIdx.x;
    const int t = threadIdx.x;

#pragma unroll
    for (int p = t; p < P; p += 256) {
        float s = 0.f;
#pragma unroll
        for (int z = 0; z < SPLITK; ++z) s += g_simp[((size_t)z * B + b) * P + p];
        cur[p] = s;
    }
    __syncthreads();

#pragma unroll
    for (int i = 0; i < TOPK; ++i) {
        float bestv = -INFINITY;
        int   besti = P;
#pragma unroll
        for (int p = t; p < P; p += 256) {
            float u = gu[(((size_t)i * B) + b) * P + p];
            float g = -logf(-logf(u + 1e-10f) + 1e-10f);
            float v = cur[p] + g;
            if (v > bestv || (v == bestv && p < besti)) { bestv = v; besti = p; }
        }
#pragma unroll
        for (int off = 16; off; off >>= 1) {
            float ov = __shfl_down_sync(0xFFFFFFFFu, bestv, off);
            int   oi = __shfl_down_sync(0xFFFFFFFFu, besti, off);
            if (ov > bestv || (ov == bestv && oi < besti)) { bestv = ov; besti = oi; }
        }
        if ((t & 31) == 0) { warpv[t >> 5] = bestv; warpi[t >> 5] = besti; }
        __syncthreads();
        if (t == 0) {
            float bv = warpv[0]; int bi = warpi[0];
#pragma unroll
            for (int w = 1; w < 8; ++w)
                if (warpv[w] > bv || (warpv[w] == bv && warpi[w] < bi)) { bv = warpv[w]; bi = warpi[w]; }
            s_sel = bi;
            cur[bi] -= 1000.0f;
            g_sel[b * TOPK + i] = bi;
        }
        __syncthreads();
    }
}

// ---------------------------------------------------------------------------
// K4b: gather-copy.  grid (TOPK*2, B): block (q,b) copies half of selection
// q>>1's L*D row block (16 KB).  2048 blocks, 4 float4 per thread.
// ---------------------------------------------------------------------------
__global__ __launch_bounds__(256) void k_copy(const float* __restrict__ prompt,
                                              float* __restrict__ out)
{
    const int b    = blockIdx.y;
    const int q    = blockIdx.x;
    const int i    = q >> 1;
    const int half = q & 1;
    const int t    = threadIdx.x;
    const int sel  = g_sel[b * TOPK + i];

    const float4* __restrict__ src =
        (const float4*)(prompt + ((size_t)sel * L + half * (L / 2)) * D);
    float4* __restrict__ dst =
        (float4*)(out + (((size_t)b * TOPK + i) * L + half * (L / 2)) * D);

#pragma unroll
    for (int r = 0; r < (L / 2) * (D / 4) / 256; ++r)   // 4 float4 per thread
        dst[t + r * 256] = __ldg(&src[t + r * 256]);
}

// ---------------------------------------------------------------------------
extern "C" void kernel_launch(void* const* d_in, const int* in_sizes, int n_in,
                              void* d_out, int out_size)
{
    const float* x      = (const float*)d_in[0]; // [B,S,D]
    const float* prompt = (const float*)d_in[1]; // [P,L,D]
    const float* pkey   = (const float*)d_in[2]; // [P,D]
    const float* gu     = (const float*)d_in[3]; // [TOPK,B,P]
    float* out          = (float*)d_out;         // [B, TOPK*L, D]

    k1a_partial<<<dim3(B, SCHUNK), 256>>>(x);
    k_norms<<<B + P, 256>>>(pkey);
    k_sim_gemm<<<dim3(B / 64, P / 64, SPLITK), 256>>>();
    k_select<<<B, 256>>>(gu);
    k_copy<<<dim3(TOPK * 2, B), 256>>>(prompt, out);
}

// round 11
// speedup vs baseline: 1.0867x; 1.0036x over previous
#include <cuda_runtime.h>
#include <cuda_bf16.h>
#include <math.h>

// Shapes (fixed by problem)
#define B    256
#define S    196
#define D    1024
#define P    512
#define L    8
#define TOPK 4
#define SPLITK 8      // GEMM split-K (1024/8 = 128 per split)
#define SCHUNK 4      // K1 split over S (196/4 = 49 rows per chunk)

#define GEMM_SMEM (2 * 128 * 68 * 4)   // As + Bs, [128][68] floats each

// Scratch (device globals; no allocation allowed)
__device__ float g_part[B * SCHUNK * D];   // K1 partial sums   [B,4,D]  4 MB
__device__ float g_qn[B * D];              // normalized query  [B,D]    1 MB
__device__ float g_kn[P * D];              // normalized keys   [P,D]    2 MB
__device__ float g_simp[SPLITK * B * P];   // split-K partials  [8,B,P]  4 MB
__device__ float g_cand_v[TOPK * B * 4];   // top-4 values per (round,b)
__device__ int   g_cand_i[TOPK * B * 4];   // top-4 indices per (round,b)

// ---------------------------------------------------------------------------
// K1a: partial sums over 49-row chunks of S.  grid (B, SCHUNK), 256 threads.
// ---------------------------------------------------------------------------
__global__ __launch_bounds__(256) void k1a_partial(const float* __restrict__ x)
{
    const int b = blockIdx.x;
    const int c = blockIdx.y;
    const int t = threadIdx.x;
    const float4* __restrict__ xp =
        (const float4*)(x + ((size_t)b * S + c * (S / SCHUNK)) * D) + t;

    float4 acc = make_float4(0.f, 0.f, 0.f, 0.f);
#pragma unroll 7
    for (int s = 0; s < S / SCHUNK; ++s) {
        float4 v = xp[(size_t)s * (D / 4)];
        acc.x += v.x; acc.y += v.y; acc.z += v.z; acc.w += v.w;
    }
    ((float4*)g_part)[((size_t)(b * SCHUNK + c) * D) / 4 + t] = acc;
}

// ---------------------------------------------------------------------------
// K1b+K2 fused: blocks [0,B) finalize query (reduce partials, /S, l2norm);
// blocks [B, B+P) l2-normalize prompt_key rows.  256 threads = D/4 float4s.
// ---------------------------------------------------------------------------
__global__ __launch_bounds__(256) void k_norms(const float* __restrict__ pk)
{
    __shared__ float red[8];
    __shared__ float s_inv;
    const int blk = blockIdx.x;
    const int t = threadIdx.x;

    float4 v;
    float* dst;
    if (blk < B) {
        const float4* pp = (const float4*)g_part + (size_t)blk * SCHUNK * (D / 4) + t;
        float4 a0 = pp[0 * (D / 4)], a1 = pp[1 * (D / 4)];
        float4 a2 = pp[2 * (D / 4)], a3 = pp[3 * (D / 4)];
        const float inv_s = 1.0f / (float)S;
        v.x = (a0.x + a1.x + a2.x + a3.x) * inv_s;
        v.y = (a0.y + a1.y + a2.y + a3.y) * inv_s;
        v.z = (a0.z + a1.z + a2.z + a3.z) * inv_s;
        v.w = (a0.w + a1.w + a2.w + a3.w) * inv_s;
        dst = g_qn + (size_t)blk * D;
    } else {
        const int p = blk - B;
        v = ((const float4*)(pk + (size_t)p * D))[t];
        dst = g_kn + (size_t)p * D;
    }

    float sq = v.x * v.x + v.y * v.y + v.z * v.z + v.w * v.w;
#pragma unroll
    for (int off = 16; off; off >>= 1) sq += __shfl_down_sync(0xFFFFFFFFu, sq, off);
    if ((t & 31) == 0) red[t >> 5] = sq;
    __syncthreads();
    if (t == 0) {
        float tot = 0.f;
#pragma unroll
        for (int w = 0; w < 8; ++w) tot += red[w];
        s_inv = rsqrtf(fmaxf(tot, 1e-12f));
    }
    __syncthreads();
    const float inv = s_inv;
    ((float4*)dst)[t] = make_float4(v.x * inv, v.y * inv, v.z * inv, v.w * inv);
}

// ---------------------------------------------------------------------------
// K3: split-K SGEMM  sim = qn * kn^T.  BM=64, BN=64, full K-chunk (128)
// staged into shared ONCE per block (70KB, 2 blocks/SM), then a single
// uninterrupted FMA loop: no per-BK latency bubble. grid (4,8,8), 256 thr.
// ---------------------------------------------------------------------------
__global__ __launch_bounds__(256) void k_sim_gemm()
{
    extern __shared__ float sm[];
    float* As = sm;                 // [128][68] k-major
    float* Bs = sm + 128 * 68;      // [128][68] k-major

    const int m0 = blockIdx.x * 64;
    const int n0 = blockIdx.y * 64;
    const int kbase = blockIdx.z * (D / SPLITK);   // 128-wide chunk

    const int tid = threadIdx.x;
    const int lr = tid >> 2;          // 0..63: tile row this thread loads
    const int c  = tid & 3;           // 0..3 : which float4 group
    const int tr = tid >> 4;          // 0..15: m-group for compute
    const int tc = tid & 15;          // 0..15: n-group for compute

    // ---- load full 64x128 A and B tiles: 8 float4 each, all in flight ----
    float4 a[8], bv4[8];
    {
        const float4* Ap = (const float4*)&g_qn[(m0 + lr) * D + kbase];
        const float4* Bp = (const float4*)&g_kn[(n0 + lr) * D + kbase];
#pragma unroll
        for (int j = 0; j < 8; ++j) a[j]   = Ap[c + 4 * j];
#pragma unroll
        for (int j = 0; j < 8; ++j) bv4[j] = Bp[c + 4 * j];
    }
#pragma unroll
    for (int j = 0; j < 8; ++j) {
        const int k0 = 4 * (c + 4 * j);
        As[(k0 + 0) * 68 + lr] = a[j].x;  As[(k0 + 1) * 68 + lr] = a[j].y;
        As[(k0 + 2) * 68 + lr] = a[j].z;  As[(k0 + 3) * 68 + lr] = a[j].w;
        Bs[(k0 + 0) * 68 + lr] = bv4[j].x; Bs[(k0 + 1) * 68 + lr] = bv4[j].y;
        Bs[(k0 + 2) * 68 + lr] = bv4[j].z; Bs[(k0 + 3) * 68 + lr] = bv4[j].w;
    }
    __syncthreads();

    float acc[4][4] = {};
#pragma unroll 16
    for (int k = 0; k < 128; ++k) {
        const float4 av = *(const float4*)&As[k * 68 + tr * 4];
        const float4 bb = *(const float4*)&Bs[k * 68 + tc * 4];
        const float aa[4] = {av.x, av.y, av.z, av.w};
        const float bw[4] = {bb.x, bb.y, bb.z, bb.w};
#pragma unroll
        for (int i = 0; i < 4; ++i)
#pragma unroll
            for (int j = 0; j < 4; ++j)
                acc[i][j] = fmaf(aa[i], bw[j], acc[i][j]);
    }

#pragma unroll
    for (int i = 0; i < 4; ++i) {
        float4 r = make_float4(acc[i][0], acc[i][1], acc[i][2], acc[i][3]);
        *(float4*)&g_simp[((size_t)blockIdx.z * B + (m0 + tr * 4 + i)) * P + n0 + tc * 4] = r;
    }
}

// ---------------------------------------------------------------------------
// K4a: top-4 candidates per (round i, batch b).  grid (TOPK, B) = 1024 blocks,
// fully parallel (no cross-round serialization).  Exclusion-by-index of <=3
// previously-chosen entries is resolved later from the top-4 list, which is
// exactly equivalent to the sequential -1000-masked argmax.
// ---------------------------------------------------------------------------
__global__ __launch_bounds__(256) void k_top4(const float* __restrict__ gu)
{
    __shared__ float v[P];
    __shared__ float wv[8];
    __shared__ int   wi[8];

    const int i = blockIdx.x;
    const int b = blockIdx.y;
    const int t = threadIdx.x;

#pragma unroll
    for (int p = t; p < P; p += 256) {
        float s = 0.f;
#pragma unroll
        for (int z = 0; z < SPLITK; ++z) s += g_simp[((size_t)z * B + b) * P + p];
        float u = gu[(((size_t)i * B) + b) * P + p];
        v[p] = s + (-logf(-logf(u + 1e-10f) + 1e-10f));
    }
    __syncthreads();

#pragma unroll
    for (int r = 0; r < 4; ++r) {
        float bestv = -INFINITY;
        int   besti = P;
#pragma unroll
        for (int p = t; p < P; p += 256) {
            float val = v[p];
            if (val > bestv || (val == bestv && p < besti)) { bestv = val; besti = p; }
        }
#pragma unroll
        for (int off = 16; off; off >>= 1) {
            float ov = __shfl_down_sync(0xFFFFFFFFu, bestv, off);
            int   oi = __shfl_down_sync(0xFFFFFFFFu, besti, off);
            if (ov > bestv || (ov == bestv && oi < besti)) { bestv = ov; besti = oi; }
        }
        if ((t & 31) == 0) { wv[t >> 5] = bestv; wi[t >> 5] = besti; }
        __syncthreads();
        if (t == 0) {
            float bvv = wv[0]; int bii = wi[0];
#pragma unroll
            for (int w = 1; w < 8; ++w)
                if (wv[w] > bvv || (wv[w] == bvv && wi[w] < bii)) { bvv = wv[w]; bii = wi[w]; }
            g_cand_v[(i * B + b) * 4 + r] = bvv;
            g_cand_i[(i * B + b) * 4 + r] = bii;
            v[bii] = -INFINITY;          // exact removal by index
        }
        __syncthreads();
    }
}

// ---------------------------------------------------------------------------
// K4b: gather-copy with inline selection resolve.  grid (TOPK*2, B): block
// (q,b) resolves the 4 selections for b from the candidate lists (tiny,
// thread 0) and copies half of selection q>>1's [L,D] block.
// ---------------------------------------------------------------------------
__global__ __launch_bounds__(256) void k_copy(const float* __restrict__ prompt,
                                              float* __restrict__ out)
{
    __shared__ int s_sel;
    const int b    = blockIdx.y;
    const int q    = blockIdx.x;
    const int i    = q >> 1;
    const int half = q & 1;
    const int t    = threadIdx.x;

    if (t == 0) {
        int chosen[TOPK];
#pragma unroll
        for (int r = 0; r < TOPK; ++r) {
            const int base = (r * B + b) * 4;
            int pick = -1;
#pragma unroll
            for (int j = 0; j < 4; ++j) {
                int id = g_cand_i[base + j];
                bool used = false;
                for (int e = 0; e < r; ++e) used |= (chosen[e] == id);
                if (!used && pick < 0) pick = id;
            }
            chosen[r] = pick;
        }
        s_sel = chosen[i];
    }
    __syncthreads();
    const int sel = s_sel;

    const float4* __restrict__ src =
        (const float4*)(prompt + ((size_t)sel * L + half * (L / 2)) * D);
    float4* __restrict__ dst =
        (float4*)(out + (((size_t)b * TOPK + i) * L + half * (L / 2)) * D);

#pragma unroll
    for (int r = 0; r < (L / 2) * (D / 4) / 256; ++r)   // 4 float4 per thread
        __stcs(&dst[t + r * 256], __ldg(&src[t + r * 256]));
}

// ---------------------------------------------------------------------------
extern "C" void kernel_launch(void* const* d_in, const int* in_sizes, int n_in,
                              void* d_out, int out_size)
{
    const float* x      = (const float*)d_in[0]; // [B,S,D]
    const float* prompt = (const float*)d_in[1]; // [P,L,D]
    const float* pkey   = (const float*)d_in[2]; // [P,D]
    const float* gu     = (const float*)d_in[3]; // [TOPK,B,P]
    float* out          = (float*)d_out;         // [B, TOPK*L, D]

    cudaFuncSetAttribute(k_sim_gemm,
                         cudaFuncAttributeMaxDynamicSharedMemorySize, GEMM_SMEM);

    k1a_partial<<<dim3(B, SCHUNK), 256>>>(x);
    k_norms<<<B + P, 256>>>(pkey);
    k_sim_gemm<<<dim3(B / 64, P / 64, SPLITK), 256, GEMM_SMEM>>>();
    k_top4<<<dim3(TOPK, B), 256>>>(gu);
    k_copy<<<dim3(TOPK * 2, B), 256>>>(prompt, out);
}

// round 12
// speedup vs baseline: 1.1952x; 1.0998x over previous
#include <cuda_runtime.h>
#include <cuda_bf16.h>
#include <math.h>

// Shapes (fixed by problem)
#define B    256
#define S    196
#define D    1024
#define P    512
#define L    8
#define TOPK 4
#define SPLITK 8      // GEMM split-K (1024/8 = 128 per split)
#define SCHUNK 4      // K1 split over S (196/4 = 49 rows per chunk)

#define GEMM_SMEM (2 * 128 * 68 * 4)   // As + Bs, [128][68] floats each

// f32x2 packed helpers (bit-identical per-lane rn FMA; ptxas won't auto-fuse)
#define FMA2(acc, a, b) asm("fma.rn.f32x2 %0, %1, %2, %0;" : "+l"(acc) : "l"(a), "l"(b))
#define PACK_DUP(out, f) asm("mov.b64 %0, {%1, %1};" : "=l"(out) : "f"(f))
#define UNPACK2(lo, hi, in) asm("mov.b64 {%0, %1}, %2;" : "=f"(lo), "=f"(hi) : "l"(in))

// Scratch (device globals; no allocation allowed)
__device__ float g_part[B * SCHUNK * D];   // K1 partial sums   [B,4,D]  4 MB
__device__ float g_qn[B * D];              // normalized query  [B,D]    1 MB
__device__ float g_kn[P * D];              // normalized keys   [P,D]    2 MB
__device__ float g_simp[SPLITK * B * P];   // split-K partials  [8,B,P]  4 MB
__device__ float g_sim[B * P];             // reduced sim       [B,P]    0.5 MB
__device__ float g_cand_v[TOPK * B * 4];   // top-4 values per (round,b)
__device__ int   g_cand_i[TOPK * B * 4];   // top-4 indices per (round,b)

// ---------------------------------------------------------------------------
// K1a: partial sums over 49-row chunks of S.  grid (B, SCHUNK), 256 threads.
// ---------------------------------------------------------------------------
__global__ __launch_bounds__(256) void k1a_partial(const float* __restrict__ x)
{
    const int b = blockIdx.x;
    const int c = blockIdx.y;
    const int t = threadIdx.x;
    const float4* __restrict__ xp =
        (const float4*)(x + ((size_t)b * S + c * (S / SCHUNK)) * D) + t;

    float4 acc = make_float4(0.f, 0.f, 0.f, 0.f);
#pragma unroll 7
    for (int s = 0; s < S / SCHUNK; ++s) {
        float4 v = __ldcs(&xp[(size_t)s * (D / 4)]);   // streaming: no L2 reuse
        acc.x += v.x; acc.y += v.y; acc.z += v.z; acc.w += v.w;
    }
    ((float4*)g_part)[((size_t)(b * SCHUNK + c) * D) / 4 + t] = acc;
}

// ---------------------------------------------------------------------------
// K1b+K2 fused: blocks [0,B) finalize query (reduce partials, /S, l2norm);
// blocks [B, B+P) l2-normalize prompt_key rows.  256 threads = D/4 float4s.
// ---------------------------------------------------------------------------
__global__ __launch_bounds__(256) void k_norms(const float* __restrict__ pk)
{
    __shared__ float red[8];
    __shared__ float s_inv;
    const int blk = blockIdx.x;
    const int t = threadIdx.x;

    float4 v;
    float* dst;
    if (blk < B) {
        const float4* pp = (const float4*)g_part + (size_t)blk * SCHUNK * (D / 4) + t;
        float4 a0 = pp[0 * (D / 4)], a1 = pp[1 * (D / 4)];
        float4 a2 = pp[2 * (D / 4)], a3 = pp[3 * (D / 4)];
        const float inv_s = 1.0f / (float)S;
        v.x = (a0.x + a1.x + a2.x + a3.x) * inv_s;
        v.y = (a0.y + a1.y + a2.y + a3.y) * inv_s;
        v.z = (a0.z + a1.z + a2.z + a3.z) * inv_s;
        v.w = (a0.w + a1.w + a2.w + a3.w) * inv_s;
        dst = g_qn + (size_t)blk * D;
    } else {
        const int p = blk - B;
        v = ((const float4*)(pk + (size_t)p * D))[t];
        dst = g_kn + (size_t)p * D;
    }

    float sq = v.x * v.x + v.y * v.y + v.z * v.z + v.w * v.w;
#pragma unroll
    for (int off = 16; off; off >>= 1) sq += __shfl_down_sync(0xFFFFFFFFu, sq, off);
    if ((t & 31) == 0) red[t >> 5] = sq;
    __syncthreads();
    if (t == 0) {
        float tot = 0.f;
#pragma unroll
        for (int w = 0; w < 8; ++w) tot += red[w];
        s_inv = rsqrtf(fmaxf(tot, 1e-12f));
    }
    __syncthreads();
    const float inv = s_inv;
    ((float4*)dst)[t] = make_float4(v.x * inv, v.y * inv, v.z * inv, v.w * inv);
}

// ---------------------------------------------------------------------------
// K3: split-K SGEMM  sim = qn * kn^T.  BM=64, BN=64, K-chunk 128 staged into
// shared once per block.  Inner loop: packed fma.rn.f32x2 — 8 FFMA2 + 4 mov
// per k instead of 16 FFMA (FMA-pipe time halves; movs ride the ALU pipe).
// grid (4,8,8), 256 threads, 70 KB dynamic smem.
// ---------------------------------------------------------------------------
__global__ __launch_bounds__(256) void k_sim_gemm()
{
    extern __shared__ float sm[];
    float* As = sm;                 // [128][68] k-major
    float* Bs = sm + 128 * 68;      // [128][68] k-major

    const int m0 = blockIdx.x * 64;
    const int n0 = blockIdx.y * 64;
    const int kbase = blockIdx.z * (D / SPLITK);   // 128-wide chunk

    const int tid = threadIdx.x;
    const int lr = tid >> 2;          // 0..63: tile row this thread loads
    const int c  = tid & 3;           // 0..3 : which float4 group
    const int tr = tid >> 4;          // 0..15: m-group for compute
    const int tc = tid & 15;          // 0..15: n-group for compute

    // ---- load full 64x128 A and B tiles: 8 float4 each, all in flight ----
    float4 a[8], bv4[8];
    {
        const float4* Ap = (const float4*)&g_qn[(m0 + lr) * D + kbase];
        const float4* Bp = (const float4*)&g_kn[(n0 + lr) * D + kbase];
#pragma unroll
        for (int j = 0; j < 8; ++j) a[j]   = Ap[c + 4 * j];
#pragma unroll
        for (int j = 0; j < 8; ++j) bv4[j] = Bp[c + 4 * j];
    }
#pragma unroll
    for (int j = 0; j < 8; ++j) {
        const int k0 = 4 * (c + 4 * j);
        As[(k0 + 0) * 68 + lr] = a[j].x;  As[(k0 + 1) * 68 + lr] = a[j].y;
        As[(k0 + 2) * 68 + lr] = a[j].z;  As[(k0 + 3) * 68 + lr] = a[j].w;
        Bs[(k0 + 0) * 68 + lr] = bv4[j].x; Bs[(k0 + 1) * 68 + lr] = bv4[j].y;
        Bs[(k0 + 2) * 68 + lr] = bv4[j].z; Bs[(k0 + 3) * 68 + lr] = bv4[j].w;
    }
    __syncthreads();

    // acc[i][0] = {acc(i, 4tc+0), acc(i, 4tc+1)}, acc[i][1] = pair 2|3.
    unsigned long long acc[4][2] = {};
#pragma unroll 16
    for (int k = 0; k < 128; ++k) {
        const float4 av = *(const float4*)&As[k * 68 + tr * 4];
        // B pair loads: 16B-aligned (68*4*k = 272k bytes, 272 % 16 == 0)
        const ulonglong2 bp = *(const ulonglong2*)&Bs[k * 68 + tc * 4];
        unsigned long long ap0, ap1, ap2, ap3;
        PACK_DUP(ap0, av.x); PACK_DUP(ap1, av.y);
        PACK_DUP(ap2, av.z); PACK_DUP(ap3, av.w);
        FMA2(acc[0][0], ap0, bp.x); FMA2(acc[0][1], ap0, bp.y);
        FMA2(acc[1][0], ap1, bp.x); FMA2(acc[1][1], ap1, bp.y);
        FMA2(acc[2][0], ap2, bp.x); FMA2(acc[2][1], ap2, bp.y);
        FMA2(acc[3][0], ap3, bp.x); FMA2(acc[3][1], ap3, bp.y);
    }

#pragma unroll
    for (int i = 0; i < 4; ++i) {
        float4 r;
        UNPACK2(r.x, r.y, acc[i][0]);
        UNPACK2(r.z, r.w, acc[i][1]);
        *(float4*)&g_simp[((size_t)blockIdx.z * B + (m0 + tr * 4 + i)) * P + n0 + tc * 4] = r;
    }
}

// ---------------------------------------------------------------------------
// K3b: reduce split-K partials once (fixed order -> bit-identical to before).
// grid 512 x 256: one (b,p) element per thread.
// ---------------------------------------------------------------------------
__global__ __launch_bounds__(256) void k_reduce()
{
    const int idx = blockIdx.x * 256 + threadIdx.x;   // b*P + p
    float s = 0.f;
#pragma unroll
    for (int z = 0; z < SPLITK; ++z) s += g_simp[(size_t)z * (B * P) + idx];
    g_sim[idx] = s;
}

// ---------------------------------------------------------------------------
// K4a: top-4 candidates per (round i, batch b).  grid (TOPK, B) = 1024 blocks.
// Reads the pre-reduced sim (2 LDG/thread instead of 16) + gumbel transform.
// Exclusion of <=3 previously-chosen entries is resolved in k_copy; top-4
// suffices and is exactly equivalent to the sequential -1000-masked argmax.
// ---------------------------------------------------------------------------
__global__ __launch_bounds__(256) void k_top4(const float* __restrict__ gu)
{
    __shared__ float v[P];
    __shared__ float wv[8];
    __shared__ int   wi[8];

    const int i = blockIdx.x;
    const int b = blockIdx.y;
    const int t = threadIdx.x;

#pragma unroll
    for (int p = t; p < P; p += 256) {
        float u = gu[(((size_t)i * B) + b) * P + p];
        float g = -logf(-logf(u + 1e-10f) + 1e-10f);
        v[p] = g_sim[(size_t)b * P + p] + g;
    }
    __syncthreads();

#pragma unroll
    for (int r = 0; r < 4; ++r) {
        float bestv = -INFINITY;
        int   besti = P;
#pragma unroll
        for (int p = t; p < P; p += 256) {
            float val = v[p];
            if (val > bestv || (val == bestv && p < besti)) { bestv = val; besti = p; }
        }
#pragma unroll
        for (int off = 16; off; off >>= 1) {
            float ov = __shfl_down_sync(0xFFFFFFFFu, bestv, off);
            int   oi = __shfl_down_sync(0xFFFFFFFFu, besti, off);
            if (ov > bestv || (ov == bestv && oi < besti)) { bestv = ov; besti = oi; }
        }
        if ((t & 31) == 0) { wv[t >> 5] = bestv; wi[t >> 5] = besti; }
        __syncthreads();
        if (t == 0) {
            float bvv = wv[0]; int bii = wi[0];
#pragma unroll
            for (int w = 1; w < 8; ++w)
                if (wv[w] > bvv || (wv[w] == bvv && wi[w] < bii)) { bvv = wv[w]; bii = wi[w]; }
            g_cand_v[(i * B + b) * 4 + r] = bvv;
            g_cand_i[(i * B + b) * 4 + r] = bii;
            v[bii] = -INFINITY;          // exact removal by index
        }
        __syncthreads();
    }
}

// ---------------------------------------------------------------------------
// K4b: gather-copy with inline selection resolve.  grid (TOPK*2, B): block
// (q,b) resolves the 4 selections for b from the candidate lists (thread 0)
// and copies half of selection q>>1's [L,D] block.
// ---------------------------------------------------------------------------
__global__ __launch_bounds__(256) void k_copy(const float* __restrict__ prompt,
                                              float* __restrict__ out)
{
    __shared__ int s_sel;
    const int b    = blockIdx.y;
    const int q    = blockIdx.x;
    const int i    = q >> 1;
    const int half = q & 1;
    const int t    = threadIdx.x;

    if (t == 0) {
        int chosen[TOPK];
#pragma unroll
        for (int r = 0; r < TOPK; ++r) {
            const int base = (r * B + b) * 4;
            int pick = -1;
#pragma unroll
            for (int j = 0; j < 4; ++j) {
                int id = g_cand_i[base + j];
                bool used = false;
                for (int e = 0; e < r; ++e) used |= (chosen[e] == id);
                if (!used && pick < 0) pick = id;
            }
            chosen[r] = pick;
        }
        s_sel = chosen[i];
    }
    __syncthreads();
    const int sel = s_sel;

    const float4* __restrict__ src =
        (const float4*)(prompt + ((size_t)sel * L + half * (L / 2)) * D);
    float4* __restrict__ dst =
        (float4*)(out + (((size_t)b * TOPK + i) * L + half * (L / 2)) * D);

#pragma unroll
    for (int r = 0; r < (L / 2) * (D / 4) / 256; ++r)   // 4 float4 per thread
        __stcs(&dst[t + r * 256], __ldg(&src[t + r * 256]));
}

// ---------------------------------------------------------------------------
extern "C" void kernel_launch(void* const* d_in, const int* in_sizes, int n_in,
                              void* d_out, int out_size)
{
    const float* x      = (const float*)d_in[0]; // [B,S,D]
    const float* prompt = (const float*)d_in[1]; // [P,L,D]
    const float* pkey   = (const float*)d_in[2]; // [P,D]
    const float* gu     = (const float*)d_in[3]; // [TOPK,B,P]
    float* out          = (float*)d_out;         // [B, TOPK*L, D]

    cudaFuncSetAttribute(k_sim_gemm,
                         cudaFuncAttributeMaxDynamicSharedMemorySize, GEMM_SMEM);

    k1a_partial<<<dim3(B, SCHUNK), 256>>>(x);
    k_norms<<<B + P, 256>>>(pkey);
    k_sim_gemm<<<dim3(B / 64, P / 64, SPLITK), 256, GEMM_SMEM>>>();
    k_reduce<<<(B * P) / 256, 256>>>();
    k_top4<<<dim3(TOPK, B), 256>>>(gu);
    k_copy<<<dim3(TOPK * 2, B), 256>>>(prompt, out);
}

// round 13
// speedup vs baseline: 1.2310x; 1.0300x over previous
#include <cuda_runtime.h>
#include <cuda_bf16.h>
#include <math.h>

// Shapes (fixed by problem)
#define B    256
#define S    196
#define D    1024
#define P    512
#define L    8
#define TOPK 4
#define SPLITK 8      // GEMM split-K (1024/8 = 128 per split)
#define SCHUNK 7      // K1 split over S (196/7 = 28 rows per chunk)

#define GEMM_SMEM (2 * 128 * 68 * 4)   // As + Bs, [128][68] floats each

// f32x2 packed helpers (bit-identical per-lane rn FMA; ptxas won't auto-fuse)
#define FMA2(acc, a, b) asm("fma.rn.f32x2 %0, %1, %2, %0;" : "+l"(acc) : "l"(a), "l"(b))
#define PACK_DUP(out, f) asm("mov.b64 %0, {%1, %1};" : "=l"(out) : "f"(f))
#define UNPACK2(lo, hi, in) asm("mov.b64 {%0, %1}, %2;" : "=f"(lo), "=f"(hi) : "l"(in))

// Scratch (device globals; no allocation allowed)
__device__ float g_part[B * SCHUNK * D];   // K1 partial sums   [B,7,D]  7 MB
__device__ float g_qn[B * D];              // normalized query  [B,D]    1 MB
__device__ float g_kn[P * D];              // normalized keys   [P,D]    2 MB
__device__ float g_simp[SPLITK * B * P];   // split-K partials  [8,B,P]  4 MB
__device__ int   g_sel[B * TOPK];          // chosen prompt indices

// ---------------------------------------------------------------------------
// K1a: partial sums over 28-row chunks of S.  grid (B, SCHUNK) = 1792 blocks,
// 256 threads.  ~12 blocks/SM through the dominant 205 MB stream.
// ---------------------------------------------------------------------------
__global__ __launch_bounds__(256) void k1a_partial(const float* __restrict__ x)
{
    const int b = blockIdx.x;
    const int c = blockIdx.y;
    const int t = threadIdx.x;
    const float4* __restrict__ xp =
        (const float4*)(x + ((size_t)b * S + c * (S / SCHUNK)) * D) + t;

    float4 acc = make_float4(0.f, 0.f, 0.f, 0.f);
#pragma unroll 7
    for (int s = 0; s < S / SCHUNK; ++s) {
        float4 v = __ldcs(&xp[(size_t)s * (D / 4)]);   // streaming: no L2 reuse
        acc.x += v.x; acc.y += v.y; acc.z += v.z; acc.w += v.w;
    }
    ((float4*)g_part)[((size_t)(b * SCHUNK + c) * D) / 4 + t] = acc;
}

// ---------------------------------------------------------------------------
// K1b+K2 fused: blocks [0,B) finalize query (reduce partials, /S, l2norm);
// blocks [B, B+P) l2-normalize prompt_key rows.  256 threads = D/4 float4s.
// ---------------------------------------------------------------------------
__global__ __launch_bounds__(256) void k_norms(const float* __restrict__ pk)
{
    __shared__ float red[8];
    __shared__ float s_inv;
    const int blk = blockIdx.x;
    const int t = threadIdx.x;

    float4 v;
    float* dst;
    if (blk < B) {
        const float4* pp = (const float4*)g_part + (size_t)blk * SCHUNK * (D / 4) + t;
        float4 a = pp[0];
#pragma unroll
        for (int c = 1; c < SCHUNK; ++c) {
            float4 w = pp[(size_t)c * (D / 4)];
            a.x += w.x; a.y += w.y; a.z += w.z; a.w += w.w;
        }
        const float inv_s = 1.0f / (float)S;
        v = make_float4(a.x * inv_s, a.y * inv_s, a.z * inv_s, a.w * inv_s);
        dst = g_qn + (size_t)blk * D;
    } else {
        const int p = blk - B;
        v = ((const float4*)(pk + (size_t)p * D))[t];
        dst = g_kn + (size_t)p * D;
    }

    float sq = v.x * v.x + v.y * v.y + v.z * v.z + v.w * v.w;
#pragma unroll
    for (int off = 16; off; off >>= 1) sq += __shfl_down_sync(0xFFFFFFFFu, sq, off);
    if ((t & 31) == 0) red[t >> 5] = sq;
    __syncthreads();
    if (t == 0) {
        float tot = 0.f;
#pragma unroll
        for (int w = 0; w < 8; ++w) tot += red[w];
        s_inv = rsqrtf(fmaxf(tot, 1e-12f));
    }
    __syncthreads();
    const float inv = s_inv;
    ((float4*)dst)[t] = make_float4(v.x * inv, v.y * inv, v.z * inv, v.w * inv);
}

// ---------------------------------------------------------------------------
// K3: split-K SGEMM  sim = qn * kn^T.  BM=64, BN=64, K-chunk 128 staged into
// shared once per block; inner loop packed fma.rn.f32x2 (8 FFMA2 + 4 mov
// per k).  grid (4,8,8), 256 threads, 70 KB dynamic smem.
// ---------------------------------------------------------------------------
__global__ __launch_bounds__(256) void k_sim_gemm()
{
    extern __shared__ float sm[];
    float* As = sm;                 // [128][68] k-major
    float* Bs = sm + 128 * 68;      // [128][68] k-major

    const int m0 = blockIdx.x * 64;
    const int n0 = blockIdx.y * 64;
    const int kbase = blockIdx.z * (D / SPLITK);   // 128-wide chunk

    const int tid = threadIdx.x;
    const int lr = tid >> 2;          // 0..63: tile row this thread loads
    const int c  = tid & 3;           // 0..3 : which float4 group
    const int tr = tid >> 4;          // 0..15: m-group for compute
    const int tc = tid & 15;          // 0..15: n-group for compute

    // ---- load full 64x128 A and B tiles: 8 float4 each, all in flight ----
    float4 a[8], bv4[8];
    {
        const float4* Ap = (const float4*)&g_qn[(m0 + lr) * D + kbase];
        const float4* Bp = (const float4*)&g_kn[(n0 + lr) * D + kbase];
#pragma unroll
        for (int j = 0; j < 8; ++j) a[j]   = Ap[c + 4 * j];
#pragma unroll
        for (int j = 0; j < 8; ++j) bv4[j] = Bp[c + 4 * j];
    }
#pragma unroll
    for (int j = 0; j < 8; ++j) {
        const int k0 = 4 * (c + 4 * j);
        As[(k0 + 0) * 68 + lr] = a[j].x;  As[(k0 + 1) * 68 + lr] = a[j].y;
        As[(k0 + 2) * 68 + lr] = a[j].z;  As[(k0 + 3) * 68 + lr] = a[j].w;
        Bs[(k0 + 0) * 68 + lr] = bv4[j].x; Bs[(k0 + 1) * 68 + lr] = bv4[j].y;
        Bs[(k0 + 2) * 68 + lr] = bv4[j].z; Bs[(k0 + 3) * 68 + lr] = bv4[j].w;
    }
    __syncthreads();

    // acc[i][0] = {acc(i, 4tc+0), acc(i, 4tc+1)}, acc[i][1] = pair 2|3.
    unsigned long long acc[4][2] = {};
#pragma unroll 16
    for (int k = 0; k < 128; ++k) {
        const float4 av = *(const float4*)&As[k * 68 + tr * 4];
        const ulonglong2 bp = *(const ulonglong2*)&Bs[k * 68 + tc * 4];
        unsigned long long ap0, ap1, ap2, ap3;
        PACK_DUP(ap0, av.x); PACK_DUP(ap1, av.y);
        PACK_DUP(ap2, av.z); PACK_DUP(ap3, av.w);
        FMA2(acc[0][0], ap0, bp.x); FMA2(acc[0][1], ap0, bp.y);
        FMA2(acc[1][0], ap1, bp.x); FMA2(acc[1][1], ap1, bp.y);
        FMA2(acc[2][0], ap2, bp.x); FMA2(acc[2][1], ap2, bp.y);
        FMA2(acc[3][0], ap3, bp.x); FMA2(acc[3][1], ap3, bp.y);
    }

#pragma unroll
    for (int i = 0; i < 4; ++i) {
        float4 r;
        UNPACK2(r.x, r.y, acc[i][0]);
        UNPACK2(r.z, r.w, acc[i][1]);
        *(float4*)&g_simp[((size_t)blockIdx.z * B + (m0 + tr * 4 + i)) * P + n0 + tc * 4] = r;
    }
}

// ---------------------------------------------------------------------------
// K4: fused reduce + 4-round gumbel argmax.  grid B, 512 threads = one
// thread per p.  Split-K sum once into a register (same z-order: bit-
// identical), then 4 sequential rounds: 1 LDG + 2 logf + shuffle/blk argmax,
// exclusion by per-thread flag (exactly equivalent to the -1000 mask).
// ---------------------------------------------------------------------------
__global__ __launch_bounds__(512) void k_select(const float* __restrict__ gu)
{
    __shared__ float wv[16];
    __shared__ int   wi[16];
    __shared__ int   s_sel;

    const int b = blockIdx.x;
    const int t = threadIdx.x;          // == p

    float sim = 0.f;
#pragma unroll
    for (int z = 0; z < SPLITK; ++z) sim += g_simp[(size_t)z * (B * P) + b * P + t];

    bool excluded = false;
#pragma unroll
    for (int i = 0; i < TOPK; ++i) {
        float u = gu[(((size_t)i * B) + b) * P + t];
        float g = -logf(-logf(u + 1e-10f) + 1e-10f);
        float bestv = excluded ? -INFINITY : sim + g;
        int   besti = t;
#pragma unroll
        for (int off = 16; off; off >>= 1) {
            float ov = __shfl_down_sync(0xFFFFFFFFu, bestv, off);
            int   oi = __shfl_down_sync(0xFFFFFFFFu, besti, off);
            if (ov > bestv || (ov == bestv && oi < besti)) { bestv = ov; besti = oi; }
        }
        if ((t & 31) == 0) { wv[t >> 5] = bestv; wi[t >> 5] = besti; }
        __syncthreads();
        if (t == 0) {
            float bvv = wv[0]; int bii = wi[0];
#pragma unroll
            for (int w = 1; w < 16; ++w)
                if (wv[w] > bvv || (wv[w] == bvv && wi[w] < bii)) { bvv = wv[w]; bii = wi[w]; }
            s_sel = bii;
            g_sel[b * TOPK + i] = bii;
        }
        __syncthreads();
        if (t == s_sel) excluded = true;
        // no extra sync needed: s_sel isn't rewritten until after the next
        // round's __syncthreads() in the t==0 branch
    }
}

// ---------------------------------------------------------------------------
// K4b: gather-copy.  grid (TOPK*2, B): block (q,b) copies half of selection
// q>>1's [L,D] block (16 KB).  2048 blocks, 4 float4 per thread.
// ---------------------------------------------------------------------------
__global__ __launch_bounds__(256) void k_copy(const float* __restrict__ prompt,
                                              float* __restrict__ out)
{
    const int b    = blockIdx.y;
    const int q    = blockIdx.x;
    const int i    = q >> 1;
    const int half = q & 1;
    const int t    = threadIdx.x;
    const int sel  = g_sel[b * TOPK + i];

    const float4* __restrict__ src =
        (const float4*)(prompt + ((size_t)sel * L + half * (L / 2)) * D);
    float4* __restrict__ dst =
        (float4*)(out + (((size_t)b * TOPK + i) * L + half * (L / 2)) * D);

#pragma unroll
    for (int r = 0; r < (L / 2) * (D / 4) / 256; ++r)   // 4 float4 per thread
        __stcs(&dst[t + r * 256], __ldg(&src[t + r * 256]));
}

// ---------------------------------------------------------------------------
extern "C" void kernel_launch(void* const* d_in, const int* in_sizes, int n_in,
                              void* d_out, int out_size)
{
    const float* x      = (const float*)d_in[0]; // [B,S,D]
    const float* prompt = (const float*)d_in[1]; // [P,L,D]
    const float* pkey   = (const float*)d_in[2]; // [P,D]
    const float* gu     = (const float*)d_in[3]; // [TOPK,B,P]
    float* out          = (float*)d_out;         // [B, TOPK*L, D]

    cudaFuncSetAttribute(k_sim_gemm,
                         cudaFuncAttributeMaxDynamicSharedMemorySize, GEMM_SMEM);

    k1a_partial<<<dim3(B, SCHUNK), 256>>>(x);
    k_norms<<<B + P, 256>>>(pkey);
    k_sim_gemm<<<dim3(B / 64, P / 64, SPLITK), 256, GEMM_SMEM>>>();
    k_select<<<B, 512>>>(gu);
    k_copy<<<dim3(TOPK * 2, B), 256>>>(prompt, out);
}

// round 14
// speedup vs baseline: 1.2663x; 1.0287x over previous
#include <cuda_runtime.h>
#include <cuda_bf16.h>
#include <math.h>

// Shapes (fixed by problem)
#define B    256
#define S    196
#define D    1024
#define P    512
#define L    8
#define TOPK 4
#define SPLITK 8      // GEMM split-K (1024/8 = 128 per split)
#define SCHUNK 7      // K1 split over S (196/7 = 28 rows per chunk)

#define GEMM_SMEM (2 * 128 * 68 * 4)   // As + Bs, [128][68] floats each

// f32x2 packed helpers (bit-identical per-lane rn FMA; ptxas won't auto-fuse)
#define FMA2(acc, a, b) asm("fma.rn.f32x2 %0, %1, %2, %0;" : "+l"(acc) : "l"(a), "l"(b))
#define PACK_DUP(out, f) asm("mov.b64 %0, {%1, %1};" : "=l"(out) : "f"(f))
#define UNPACK2(lo, hi, in) asm("mov.b64 {%0, %1}, %2;" : "=f"(lo), "=f"(hi) : "l"(in))

// Scratch (device globals; no allocation allowed)
__device__ float g_part[B * SCHUNK * D];   // K1 partial sums   [B,7,D]  7 MB
__device__ float g_qn[B * D];              // normalized query  [B,D]    1 MB
__device__ float g_kn[P * D];              // normalized keys   [P,D]    2 MB
__device__ float g_simp[SPLITK * B * P];   // split-K partials  [8,B,P]  4 MB
__device__ int   g_sel[B * TOPK];          // chosen prompt indices

// ---------------------------------------------------------------------------
// K1a: partial sums over 28-row chunks of S.  grid (B, SCHUNK) = 1792 blocks,
// 256 threads.  ~12 blocks/SM through the dominant 205 MB stream.
// ---------------------------------------------------------------------------
__global__ __launch_bounds__(256) void k1a_partial(const float* __restrict__ x)
{
    const int b = blockIdx.x;
    const int c = blockIdx.y;
    const int t = threadIdx.x;
    const float4* __restrict__ xp =
        (const float4*)(x + ((size_t)b * S + c * (S / SCHUNK)) * D) + t;

    float4 acc = make_float4(0.f, 0.f, 0.f, 0.f);
#pragma unroll 7
    for (int s = 0; s < S / SCHUNK; ++s) {
        float4 v = __ldcs(&xp[(size_t)s * (D / 4)]);   // streaming: no L2 reuse
        acc.x += v.x; acc.y += v.y; acc.z += v.z; acc.w += v.w;
    }
    ((float4*)g_part)[((size_t)(b * SCHUNK + c) * D) / 4 + t] = acc;
}

// ---------------------------------------------------------------------------
// K1b+K2 fused: blocks [0,B) finalize query (reduce partials, /S, l2norm);
// blocks [B, B+P) l2-normalize prompt_key rows.  256 threads = D/4 float4s.
// ---------------------------------------------------------------------------
__global__ __launch_bounds__(256) void k_norms(const float* __restrict__ pk)
{
    __shared__ float red[8];
    __shared__ float s_inv;
    const int blk = blockIdx.x;
    const int t = threadIdx.x;

    float4 v;
    float* dst;
    if (blk < B) {
        const float4* pp = (const float4*)g_part + (size_t)blk * SCHUNK * (D / 4) + t;
        float4 a = pp[0];
#pragma unroll
        for (int c = 1; c < SCHUNK; ++c) {
            float4 w = pp[(size_t)c * (D / 4)];
            a.x += w.x; a.y += w.y; a.z += w.z; a.w += w.w;
        }
        const float inv_s = 1.0f / (float)S;
        v = make_float4(a.x * inv_s, a.y * inv_s, a.z * inv_s, a.w * inv_s);
        dst = g_qn + (size_t)blk * D;
    } else {
        const int p = blk - B;
        v = ((const float4*)(pk + (size_t)p * D))[t];
        dst = g_kn + (size_t)p * D;
    }

    float sq = v.x * v.x + v.y * v.y + v.z * v.z + v.w * v.w;
#pragma unroll
    for (int off = 16; off; off >>= 1) sq += __shfl_down_sync(0xFFFFFFFFu, sq, off);
    if ((t & 31) == 0) red[t >> 5] = sq;
    __syncthreads();
    if (t == 0) {
        float tot = 0.f;
#pragma unroll
        for (int w = 0; w < 8; ++w) tot += red[w];
        s_inv = rsqrtf(fmaxf(tot, 1e-12f));
    }
    __syncthreads();
    const float inv = s_inv;
    ((float4*)dst)[t] = make_float4(v.x * inv, v.y * inv, v.z * inv, v.w * inv);
}

// ---------------------------------------------------------------------------
// K3: split-K SGEMM  sim = qn * kn^T.  BM=64, BN=64, K-chunk 128 staged into
// shared once per block; inner loop packed fma.rn.f32x2 (8 FFMA2 + 4 mov
// per k).  grid (4,8,8), 256 threads, 70 KB dynamic smem.
// ---------------------------------------------------------------------------
__global__ __launch_bounds__(256) void k_sim_gemm()
{
    extern __shared__ float sm[];
    float* As = sm;                 // [128][68] k-major
    float* Bs = sm + 128 * 68;      // [128][68] k-major

    const int m0 = blockIdx.x * 64;
    const int n0 = blockIdx.y * 64;
    const int kbase = blockIdx.z * (D / SPLITK);   // 128-wide chunk

    const int tid = threadIdx.x;
    const int lr = tid >> 2;          // 0..63: tile row this thread loads
    const int c  = tid & 3;           // 0..3 : which float4 group
    const int tr = tid >> 4;          // 0..15: m-group for compute
    const int tc = tid & 15;          // 0..15: n-group for compute

    // ---- load full 64x128 A and B tiles: 8 float4 each, all in flight ----
    float4 a[8], bv4[8];
    {
        const float4* Ap = (const float4*)&g_qn[(m0 + lr) * D + kbase];
        const float4* Bp = (const float4*)&g_kn[(n0 + lr) * D + kbase];
#pragma unroll
        for (int j = 0; j < 8; ++j) a[j]   = Ap[c + 4 * j];
#pragma unroll
        for (int j = 0; j < 8; ++j) bv4[j] = Bp[c + 4 * j];
    }
#pragma unroll
    for (int j = 0; j < 8; ++j) {
        const int k0 = 4 * (c + 4 * j);
        As[(k0 + 0) * 68 + lr] = a[j].x;  As[(k0 + 1) * 68 + lr] = a[j].y;
        As[(k0 + 2) * 68 + lr] = a[j].z;  As[(k0 + 3) * 68 + lr] = a[j].w;
        Bs[(k0 + 0) * 68 + lr] = bv4[j].x; Bs[(k0 + 1) * 68 + lr] = bv4[j].y;
        Bs[(k0 + 2) * 68 + lr] = bv4[j].z; Bs[(k0 + 3) * 68 + lr] = bv4[j].w;
    }
    __syncthreads();

    // acc[i][0] = {acc(i, 4tc+0), acc(i, 4tc+1)}, acc[i][1] = pair 2|3.
    unsigned long long acc[4][2] = {};
#pragma unroll 16
    for (int k = 0; k < 128; ++k) {
        const float4 av = *(const float4*)&As[k * 68 + tr * 4];
        const ulonglong2 bp = *(const ulonglong2*)&Bs[k * 68 + tc * 4];
        unsigned long long ap0, ap1, ap2, ap3;
        PACK_DUP(ap0, av.x); PACK_DUP(ap1, av.y);
        PACK_DUP(ap2, av.z); PACK_DUP(ap3, av.w);
        FMA2(acc[0][0], ap0, bp.x); FMA2(acc[0][1], ap0, bp.y);
        FMA2(acc[1][0], ap1, bp.x); FMA2(acc[1][1], ap1, bp.y);
        FMA2(acc[2][0], ap2, bp.x); FMA2(acc[2][1], ap2, bp.y);
        FMA2(acc[3][0], ap3, bp.x); FMA2(acc[3][1], ap3, bp.y);
    }

#pragma unroll
    for (int i = 0; i < 4; ++i) {
        float4 r;
        UNPACK2(r.x, r.y, acc[i][0]);
        UNPACK2(r.z, r.w, acc[i][1]);
        *(float4*)&g_simp[((size_t)blockIdx.z * B + (m0 + tr * 4 + i)) * P + n0 + tc * 4] = r;
    }
}

// ---------------------------------------------------------------------------
// K4: fused reduce + 4-round gumbel argmax, latency-optimized.  grid B,
// 512 threads = one thread per p.
//   Prologue: split-K sum (same z-order: bit-identical) AND all 4 rounds'
//   gu loads + gumbel logf chains issued up front (independent -> overlap).
//   Rounds: pure register/shuffle argmax; warp-0 shuffle reduce replaces the
//   old serial 16-scan.  Exclusion by flag == the -1000 mask exactly.
// ---------------------------------------------------------------------------
__global__ __launch_bounds__(512) void k_select(const float* __restrict__ gu)
{
    __shared__ float wv[16];
    __shared__ int   wi[16];
    __shared__ int   s_sel;

    const int b = blockIdx.x;
    const int t = threadIdx.x;          // == p

    // ---- prologue: everything memory/transcendental, fully overlapped ----
    float u0 = gu[(((size_t)0 * B) + b) * P + t];
    float u1 = gu[(((size_t)1 * B) + b) * P + t];
    float u2 = gu[(((size_t)2 * B) + b) * P + t];
    float u3 = gu[(((size_t)3 * B) + b) * P + t];

    float sim = 0.f;
#pragma unroll
    for (int z = 0; z < SPLITK; ++z) sim += g_simp[(size_t)z * (B * P) + b * P + t];

    float v[TOPK];
    v[0] = sim + (-logf(-logf(u0 + 1e-10f) + 1e-10f));
    v[1] = sim + (-logf(-logf(u1 + 1e-10f) + 1e-10f));
    v[2] = sim + (-logf(-logf(u2 + 1e-10f) + 1e-10f));
    v[3] = sim + (-logf(-logf(u3 + 1e-10f) + 1e-10f));

    // ---- 4 serial rounds: registers + shuffles only ----
    bool excluded = false;
#pragma unroll
    for (int i = 0; i < TOPK; ++i) {
        float bestv = excluded ? -INFINITY : v[i];
        int   besti = t;
#pragma unroll
        for (int off = 16; off; off >>= 1) {
            float ov = __shfl_down_sync(0xFFFFFFFFu, bestv, off);
            int   oi = __shfl_down_sync(0xFFFFFFFFu, besti, off);
            if (ov > bestv || (ov == bestv && oi < besti)) { bestv = ov; besti = oi; }
        }
        if ((t & 31) == 0) { wv[t >> 5] = bestv; wi[t >> 5] = besti; }
        __syncthreads();
        if (t < 32) {
            float bvv = (t < 16) ? wv[t] : -INFINITY;
            int   bii = (t < 16) ? wi[t] : P;
#pragma unroll
            for (int off = 8; off; off >>= 1) {
                float ov = __shfl_down_sync(0xFFFFFFFFu, bvv, off);
                int   oi = __shfl_down_sync(0xFFFFFFFFu, bii, off);
                if (ov > bvv || (ov == bvv && oi < bii)) { bvv = ov; bii = oi; }
            }
            if (t == 0) { s_sel = bii; g_sel[b * TOPK + i] = bii; }
        }
        __syncthreads();
        if (t == s_sel) excluded = true;
        // safe: s_sel is next written only after the following round's first
        // __syncthreads(), which all readers have passed by then
    }
}

// ---------------------------------------------------------------------------
// K4b: gather-copy.  grid (TOPK*2, B): block (q,b) copies half of selection
// q>>1's [L,D] block (16 KB).  2048 blocks, 4 float4 per thread.
// ---------------------------------------------------------------------------
__global__ __launch_bounds__(256) void k_copy(const float* __restrict__ prompt,
                                              float* __restrict__ out)
{
    const int b    = blockIdx.y;
    const int q    = blockIdx.x;
    const int i    = q >> 1;
    const int half = q & 1;
    const int t    = threadIdx.x;
    const int sel  = g_sel[b * TOPK + i];

    const float4* __restrict__ src =
        (const float4*)(prompt + ((size_t)sel * L + half * (L / 2)) * D);
    float4* __restrict__ dst =
        (float4*)(out + (((size_t)b * TOPK + i) * L + half * (L / 2)) * D);

#pragma unroll
    for (int r = 0; r < (L / 2) * (D / 4) / 256; ++r)   // 4 float4 per thread
        __stcs(&dst[t + r * 256], __ldg(&src[t + r * 256]));
}

// ---------------------------------------------------------------------------
extern "C" void kernel_launch(void* const* d_in, const int* in_sizes, int n_in,
                              void* d_out, int out_size)
{
    const float* x      = (const float*)d_in[0]; // [B,S,D]
    const float* prompt = (const float*)d_in[1]; // [P,L,D]
    const float* pkey   = (const float*)d_in[2]; // [P,D]
    const float* gu     = (const float*)d_in[3]; // [TOPK,B,P]
    float* out          = (float*)d_out;         // [B, TOPK*L, D]

    cudaFuncSetAttribute(k_sim_gemm,
                         cudaFuncAttributeMaxDynamicSharedMemorySize, GEMM_SMEM);

    k1a_partial<<<dim3(B, SCHUNK), 256>>>(x);
    k_norms<<<B + P, 256>>>(pkey);
    k_sim_gemm<<<dim3(B / 64, P / 64, SPLITK), 256, GEMM_SMEM>>>();
    k_select<<<B, 512>>>(gu);
    k_copy<<<dim3(TOPK * 2, B), 256>>>(prompt, out);
}